// round 15
// baseline (speedup 1.0000x reference)
#include <cuda_runtime.h>
#include <cuda_bf16.h>
#include <math.h>

#define N_TOKENS 131072
#define HIDDEN   1024
#define CL       64
#define EXPERTS  64

// ---------------------------------------------------------------------------
// packed f32x2 helpers (two independent fp32 ops per instruction, each
// correctly rounded -> bit-identical to scalar fmaf/__fadd_rn)
// ---------------------------------------------------------------------------
__device__ __forceinline__ void fma2(unsigned long long& d,
                                     unsigned long long a,
                                     unsigned long long b) {
    asm("fma.rn.f32x2 %0, %1, %2, %0;" : "+l"(d) : "l"(a), "l"(b));
}
__device__ __forceinline__ void add2(unsigned long long& d,
                                     unsigned long long a) {
    asm("add.rn.f32x2 %0, %0, %1;" : "+l"(d) : "l"(a));
}
__device__ __forceinline__ float lo32(unsigned long long p) {
    return __uint_as_float((unsigned)(p & 0xffffffffu));
}
__device__ __forceinline__ float hi32(unsigned long long p) {
    return __uint_as_float((unsigned)(p >> 32));
}

// ---------------------------------------------------------------------------
// Eigen/XLA erf (fused pmadd Horner)
// ---------------------------------------------------------------------------
__device__ __forceinline__ float eigen_erf(float x) {
    x = fmaxf(fminf(x, 4.0f), -4.0f);
    float x2 = __fmul_rn(x, x);
    float p = fmaf(x2, -2.72614225801306e-10f, 2.77068142495902e-08f);
    p = fmaf(x2, p, -2.10102402082508e-06f);
    p = fmaf(x2, p, -5.69250639462346e-05f);
    p = fmaf(x2, p, -7.34990630326855e-04f);
    p = fmaf(x2, p, -2.95459980854025e-03f);
    p = fmaf(x2, p, -1.60960333262415e-02f);
    p = __fmul_rn(x, p);
    float q = fmaf(x2, -1.45660718464996e-05f, -2.13374055278905e-04f);
    q = fmaf(x2, q, -1.68282697438203e-03f);
    q = fmaf(x2, q, -7.37332916720468e-03f);
    q = fmaf(x2, q, -1.42647390514189e-02f);
    return __fdiv_rn(p, q);
}

__device__ __forceinline__ float xla_gelu(float v) {
    float t = __fmul_rn(v, __int_as_float(0x3F3504F3));  // * 1/sqrt(2) folded
    float e = eigen_erf(t);
    float r = __fmul_rn(v, __fadd_rn(e, 1.0f));
    return __fmul_rn(r, 0.5f);
}

// XLA:CPU runtime exp (Eigen/Cephes): fused poly, unfused Cody-Waite
__device__ __forceinline__ float xla_exp(float x) {
    x = fminf(x, 88.3762626647950f);
    x = fmaxf(x, -88.3762626647949f);
    float fx = fmaf(x, 1.44269504088896341f, 0.5f);
    fx = floorf(fx);
    float tmp = __fmul_rn(fx, 0.693359375f);
    float z   = __fmul_rn(fx, -2.12194440e-4f);
    x = __fsub_rn(x, tmp);
    x = __fsub_rn(x, z);
    z = __fmul_rn(x, x);
    float y = 1.9875691500E-4f;
    y = fmaf(y, x, 1.3981999507E-3f);
    y = fmaf(y, x, 8.3334519073E-3f);
    y = fmaf(y, x, 4.1665795894E-2f);
    y = fmaf(y, x, 1.6666665459E-1f);
    y = fmaf(y, x, 5.0000001201E-1f);
    y = fmaf(y, z, x);
    y = __fadd_rn(y, 1.0f);
    int n = (int)fx;
    float p2n = __int_as_float((n + 127) << 23);
    return __fmul_rn(y, p2n);
}

// 8-lane strided row-reduce, unfused body, halving horizontal
__device__ __forceinline__ float vsum_sq64(const float* v) {
    float a[8];
    #pragma unroll
    for (int l = 0; l < 8; l++) a[l] = 0.f;
    #pragma unroll
    for (int i = 0; i < 8; i++)
        #pragma unroll
        for (int l = 0; l < 8; l++)
            a[l] = __fadd_rn(a[l], __fmul_rn(v[8 * i + l], v[8 * i + l]));
    float b0 = __fadd_rn(a[0], a[4]);
    float b1 = __fadd_rn(a[1], a[5]);
    float b2 = __fadd_rn(a[2], a[6]);
    float b3 = __fadd_rn(a[3], a[7]);
    return __fadd_rn(__fadd_rn(b0, b2), __fadd_rn(b1, b3));
}

__device__ __forceinline__ float vsum64(const float* v) {
    float a[8];
    #pragma unroll
    for (int l = 0; l < 8; l++) a[l] = 0.f;
    #pragma unroll
    for (int i = 0; i < 8; i++)
        #pragma unroll
        for (int l = 0; l < 8; l++)
            a[l] = __fadd_rn(a[l], v[8 * i + l]);
    float b0 = __fadd_rn(a[0], a[4]);
    float b1 = __fadd_rn(a[1], a[5]);
    float b2 = __fadd_rn(a[2], a[6]);
    float b3 = __fadd_rn(a[3], a[7]);
    return __fadd_rn(__fadd_rn(b0, b2), __fadd_rn(b1, b3));
}

// ---------------------------------------------------------------------------
// Fused kernel: f32x2 GEMM (kc=512 panels) + gelu -> smem -> centroid norm
// -> per-token cdist/softmax/top2.  Arithmetic bit-identical to R13/R14.
// ---------------------------------------------------------------------------
#define BM 128
#define BN 64
#define BK 16
#define KSEG 512

// dynamic smem layout (floats):
//   GEMM phase:     [0 .. 2048)  As[16][128]
//                   [2048 .. 4096) Bs2[16][128]  (B duplicated: b,b pairs)
//   epilogue phase: [0 .. 8320)  h_s[128][65]
//                   [8320 .. 12416) cn_s[64][64]
//                   [12416 .. 12480) cc_s[64]
#define SMEM_FLOATS 12480

__global__ __launch_bounds__(256, 2)
void router_fused_kernel(const float* __restrict__ x,
                         const float* __restrict__ W,
                         const float* __restrict__ b,
                         const float* __restrict__ centroids,
                         float* __restrict__ out) {
    extern __shared__ float sm[];
    float* As   = sm;            // [16][128]
    float* Bs2  = sm + 2048;     // [16][128] duplicated pairs
    float* h_s  = sm;            // [128][65]  (after GEMM phase)
    float* cn_s = sm + 8320;     // [64][64]
    float* cc_s = sm + 12416;    // [64]

    const int tid = threadIdx.x;
    const int m0  = blockIdx.x * BM;
    const int tn  = tid & 15;
    const int tm  = tid >> 4;

    const int arow = tid >> 2;
    const int ac4  = tid & 3;
    const int brow = tid >> 4;
    const int bc4  = tid & 15;

    // packed accumulators: accP[ip][j] holds (acc[2ip][j], acc[2ip+1][j])
    unsigned long long accP[4][4], accpP[4][4];
    #pragma unroll
    for (int ip = 0; ip < 4; ip++)
        #pragma unroll
        for (int j = 0; j < 4; j++) { accP[ip][j] = 0ull; accpP[ip][j] = 0ull; }

    for (int k0 = 0; k0 < HIDDEN; k0 += BK) {
        if (k0 == KSEG) {
            // kc-panel boundary: fold (elementwise rounded adds)
            #pragma unroll
            for (int ip = 0; ip < 4; ip++)
                #pragma unroll
                for (int j = 0; j < 4; j++) {
                    add2(accpP[ip][j], accP[ip][j]);
                    accP[ip][j] = 0ull;
                }
        }

        float4 a0 = *(const float4*)&x[(size_t)(m0 + arow)      * HIDDEN + k0 + ac4 * 4];
        float4 a1 = *(const float4*)&x[(size_t)(m0 + arow + 64) * HIDDEN + k0 + ac4 * 4];
        float4 bb = *(const float4*)&W[(size_t)(k0 + brow) * CL + bc4 * 4];

        __syncthreads();

        As[(ac4 * 4 + 0) * BM + arow] = a0.x;
        As[(ac4 * 4 + 1) * BM + arow] = a0.y;
        As[(ac4 * 4 + 2) * BM + arow] = a0.z;
        As[(ac4 * 4 + 3) * BM + arow] = a0.w;
        As[(ac4 * 4 + 0) * BM + arow + 64] = a1.x;
        As[(ac4 * 4 + 1) * BM + arow + 64] = a1.y;
        As[(ac4 * 4 + 2) * BM + arow + 64] = a1.z;
        As[(ac4 * 4 + 3) * BM + arow + 64] = a1.w;
        // duplicated B: (b,b) pairs, ready-packed broadcast operands
        {
            float4 d0 = make_float4(bb.x, bb.x, bb.y, bb.y);
            float4 d1 = make_float4(bb.z, bb.z, bb.w, bb.w);
            *(float4*)&Bs2[brow * 128 + bc4 * 8 + 0] = d0;
            *(float4*)&Bs2[brow * 128 + bc4 * 8 + 4] = d1;
        }

        __syncthreads();

        #pragma unroll
        for (int kk = 0; kk < BK; kk++) {
            const ulonglong2* ap = (const ulonglong2*)&As[kk * BM + tm * 8];
            ulonglong2 afA = ap[0];           // pairs (m0,m1),(m2,m3)
            ulonglong2 afB = ap[1];           // pairs (m4,m5),(m6,m7)
            const ulonglong2* bp = (const ulonglong2*)&Bs2[kk * 128 + tn * 8];
            ulonglong2 bdA = bp[0];           // (b0,b0),(b1,b1)
            ulonglong2 bdB = bp[1];           // (b2,b2),(b3,b3)
            unsigned long long afp[4] = { afA.x, afA.y, afB.x, afB.y };
            unsigned long long bdp[4] = { bdA.x, bdA.y, bdB.x, bdB.y };
            #pragma unroll
            for (int ip = 0; ip < 4; ip++)
                #pragma unroll
                for (int j = 0; j < 4; j++)
                    fma2(accP[ip][j], afp[ip], bdp[j]);
        }
    }

    __syncthreads();   // As/Bs2 reads done before h_s overwrites region

    // bias + gelu -> h rows in smem
    {
        float bias[4];
        #pragma unroll
        for (int j = 0; j < 4; j++) bias[j] = __ldg(&b[tn * 4 + j]);

        #pragma unroll
        for (int i = 0; i < 8; i++) {
            int row = tm * 8 + i;
            #pragma unroll
            for (int j = 0; j < 4; j++) {
                float ap = (i & 1) ? hi32(accpP[i >> 1][j]) : lo32(accpP[i >> 1][j]);
                float ac = (i & 1) ? hi32(accP[i >> 1][j])  : lo32(accP[i >> 1][j]);
                float v  = __fadd_rn(__fadd_rn(ap, ac), bias[j]);
                h_s[row * 65 + tn * 4 + j] = xla_gelu(v);
            }
        }
    }

    // in-block centroid normalization (identical ops)
    if (tid < EXPERTS) {
        int e = tid;
        float c[CL];
        for (int j = 0; j < CL; j++) c[j] = centroids[e * CL + j];
        float ss = vsum_sq64(c);
        float nrm = fmaxf(__fsqrt_rn(ss), 1e-8f);
        float cn[CL];
        for (int j = 0; j < CL; j++) {
            cn[j] = __fdiv_rn(c[j], nrm);
            cn_s[e * CL + j] = cn[j];
        }
        cc_s[e] = vsum_sq64(cn);
    }

    __syncthreads();

    // per-token epilogue (threads 0..127), arithmetic identical to R13
    if (tid < BM) {
        const int t = m0 + tid;

        float d[CL];
        #pragma unroll
        for (int j = 0; j < CL; j++) d[j] = h_s[tid * 65 + j];

        float ss  = vsum_sq64(d);
        float nrm = fmaxf(__fsqrt_rn(ss), 1e-8f);
        #pragma unroll
        for (int j = 0; j < CL; j++) d[j] = __fdiv_rn(d[j], nrm);
        float dd = vsum_sq64(d);

        float nd[EXPERTS];
        float ndmax = -INFINITY;
        for (int e = 0; e < EXPERTS; e++) {
            float dot = 0.f;
            #pragma unroll
            for (int j = 0; j < CL; j++)
                dot = fmaf(d[j], cn_s[e * CL + j], dot);
            float sq   = __fsub_rn(__fadd_rn(dd, cc_s[e]), __fmul_rn(2.0f, dot));
            float dist = __fsqrt_rn(fmaxf(sq, 0.0f));
            float v = -dist;
            nd[e] = v;
            ndmax = fmaxf(ndmax, v);
        }

        #pragma unroll
        for (int e = 0; e < EXPERTS; e++)
            nd[e] = xla_exp(__fsub_rn(nd[e], ndmax));
        float sum = vsum64(nd);

        float p1 = -1.f, p2 = -1.f;
        int   i1 = 0,    i2 = 0;
        for (int e = 0; e < EXPERTS; e++) {
            float p = __fdiv_rn(nd[e], sum);
            if (p > p1)      { p2 = p1; i2 = i1; p1 = p; i1 = e; }
            else if (p > p2) { p2 = p; i2 = e; }
        }

        out[(size_t)t * 2 + 0] = p1;
        out[(size_t)t * 2 + 1] = p2;
        float* oi = out + (size_t)N_TOKENS * 2;
        oi[(size_t)t * 2 + 0] = (float)i1;
        oi[(size_t)t * 2 + 1] = (float)i2;
    }
}

// ---------------------------------------------------------------------------
extern "C" void kernel_launch(void* const* d_in, const int* in_sizes, int n_in,
                              void* d_out, int out_size) {
    const float* x         = (const float*)d_in[0];
    const float* W         = (const float*)d_in[1];
    const float* b         = (const float*)d_in[2];
    const float* centroids = (const float*)d_in[3];
    float* out = (float*)d_out;

    cudaFuncSetAttribute(router_fused_kernel,
                         cudaFuncAttributeMaxDynamicSharedMemorySize,
                         SMEM_FLOATS * (int)sizeof(float));
    router_fused_kernel<<<N_TOKENS / BM, 256, SMEM_FLOATS * sizeof(float)>>>(
        x, W, b, centroids, out);
}

// round 16
// speedup vs baseline: 1.5232x; 1.5232x over previous
#include <cuda_runtime.h>
#include <cuda_bf16.h>
#include <math.h>

#define N_TOKENS 131072
#define HIDDEN   1024
#define CL       64
#define EXPERTS  64

// Scratch (allocation-free rule: __device__ globals)
__device__ float g_h[N_TOKENS * CL];       // gelu(xW+b), 32 MB

// ---------------------------------------------------------------------------
// Eigen/XLA erf (fused pmadd Horner)
// ---------------------------------------------------------------------------
__device__ __forceinline__ float eigen_erf(float x) {
    x = fmaxf(fminf(x, 4.0f), -4.0f);
    float x2 = __fmul_rn(x, x);
    float p = fmaf(x2, -2.72614225801306e-10f, 2.77068142495902e-08f);
    p = fmaf(x2, p, -2.10102402082508e-06f);
    p = fmaf(x2, p, -5.69250639462346e-05f);
    p = fmaf(x2, p, -7.34990630326855e-04f);
    p = fmaf(x2, p, -2.95459980854025e-03f);
    p = fmaf(x2, p, -1.60960333262415e-02f);
    p = __fmul_rn(x, p);
    float q = fmaf(x2, -1.45660718464996e-05f, -2.13374055278905e-04f);
    q = fmaf(x2, q, -1.68282697438203e-03f);
    q = fmaf(x2, q, -7.37332916720468e-03f);
    q = fmaf(x2, q, -1.42647390514189e-02f);
    return __fdiv_rn(p, q);
}

__device__ __forceinline__ float xla_gelu(float v) {
    float t = __fmul_rn(v, __int_as_float(0x3F3504F3));  // * 1/sqrt(2) folded
    float e = eigen_erf(t);
    float r = __fmul_rn(v, __fadd_rn(e, 1.0f));
    return __fmul_rn(r, 0.5f);
}

// XLA:CPU runtime exp (Eigen/Cephes): fused poly, unfused Cody-Waite
__device__ __forceinline__ float xla_exp(float x) {
    x = fminf(x, 88.3762626647950f);
    x = fmaxf(x, -88.3762626647949f);
    float fx = fmaf(x, 1.44269504088896341f, 0.5f);
    fx = floorf(fx);
    float tmp = __fmul_rn(fx, 0.693359375f);
    float z   = __fmul_rn(fx, -2.12194440e-4f);
    x = __fsub_rn(x, tmp);
    x = __fsub_rn(x, z);
    z = __fmul_rn(x, x);
    float y = 1.9875691500E-4f;
    y = fmaf(y, x, 1.3981999507E-3f);
    y = fmaf(y, x, 8.3334519073E-3f);
    y = fmaf(y, x, 4.1665795894E-2f);
    y = fmaf(y, x, 1.6666665459E-1f);
    y = fmaf(y, x, 5.0000001201E-1f);
    y = fmaf(y, z, x);
    y = __fadd_rn(y, 1.0f);
    int n = (int)fx;
    float p2n = __int_as_float((n + 127) << 23);
    return __fmul_rn(y, p2n);
}

// 8-lane strided row-reduce, unfused body, halving horizontal
__device__ __forceinline__ float vsum_sq64(const float* v) {
    float a[8];
    #pragma unroll
    for (int l = 0; l < 8; l++) a[l] = 0.f;
    #pragma unroll
    for (int i = 0; i < 8; i++)
        #pragma unroll
        for (int l = 0; l < 8; l++)
            a[l] = __fadd_rn(a[l], __fmul_rn(v[8 * i + l], v[8 * i + l]));
    float b0 = __fadd_rn(a[0], a[4]);
    float b1 = __fadd_rn(a[1], a[5]);
    float b2 = __fadd_rn(a[2], a[6]);
    float b3 = __fadd_rn(a[3], a[7]);
    return __fadd_rn(__fadd_rn(b0, b2), __fadd_rn(b1, b3));
}

__device__ __forceinline__ float vsum64(const float* v) {
    float a[8];
    #pragma unroll
    for (int l = 0; l < 8; l++) a[l] = 0.f;
    #pragma unroll
    for (int i = 0; i < 8; i++)
        #pragma unroll
        for (int l = 0; l < 8; l++)
            a[l] = __fadd_rn(a[l], v[8 * i + l]);
    float b0 = __fadd_rn(a[0], a[4]);
    float b1 = __fadd_rn(a[1], a[5]);
    float b2 = __fadd_rn(a[2], a[6]);
    float b3 = __fadd_rn(a[3], a[7]);
    return __fadd_rn(__fadd_rn(b0, b2), __fadd_rn(b1, b3));
}

// ---------------------------------------------------------------------------
// Kernel 1: fp32 tiled GEMM  h = gelu(x @ W + b)   [R13, byte-for-byte]
// Eigen kc=512 panel segmentation: two fused chains, rounded combine.
// ---------------------------------------------------------------------------
#define BM 128
#define BN 64
#define BK 16
#define KSEG 512

__global__ __launch_bounds__(256, 2)
void gemm_gelu_kernel(const float* __restrict__ x,
                      const float* __restrict__ W,
                      const float* __restrict__ b) {
    __shared__ float As[BK][BM];
    __shared__ float Bs[BK][BN];

    const int tid = threadIdx.x;
    const int m0  = blockIdx.x * BM;
    const int tn  = tid & 15;
    const int tm  = tid >> 4;

    const int arow = tid >> 2;
    const int ac4  = tid & 3;
    const int brow = tid >> 4;
    const int bc4  = tid & 15;

    float acc[8][4];
    float accp[8][4];
    #pragma unroll
    for (int i = 0; i < 8; i++)
        #pragma unroll
        for (int j = 0; j < 4; j++) { acc[i][j] = 0.f; accp[i][j] = 0.f; }

    for (int k0 = 0; k0 < HIDDEN; k0 += BK) {
        if (k0 == KSEG) {
            #pragma unroll
            for (int i = 0; i < 8; i++)
                #pragma unroll
                for (int j = 0; j < 4; j++) {
                    accp[i][j] = __fadd_rn(accp[i][j], acc[i][j]);
                    acc[i][j] = 0.f;
                }
        }

        float4 a0 = *(const float4*)&x[(size_t)(m0 + arow)      * HIDDEN + k0 + ac4 * 4];
        float4 a1 = *(const float4*)&x[(size_t)(m0 + arow + 64) * HIDDEN + k0 + ac4 * 4];
        float4 bb = *(const float4*)&W[(size_t)(k0 + brow) * CL + bc4 * 4];

        __syncthreads();

        As[ac4 * 4 + 0][arow] = a0.x;
        As[ac4 * 4 + 1][arow] = a0.y;
        As[ac4 * 4 + 2][arow] = a0.z;
        As[ac4 * 4 + 3][arow] = a0.w;
        As[ac4 * 4 + 0][arow + 64] = a1.x;
        As[ac4 * 4 + 1][arow + 64] = a1.y;
        As[ac4 * 4 + 2][arow + 64] = a1.z;
        As[ac4 * 4 + 3][arow + 64] = a1.w;
        *(float4*)&Bs[brow][bc4 * 4] = bb;

        __syncthreads();

        #pragma unroll
        for (int kk = 0; kk < BK; kk++) {
            float af[8], bf[4];
            *(float4*)&af[0] = *(const float4*)&As[kk][tm * 8 + 0];
            *(float4*)&af[4] = *(const float4*)&As[kk][tm * 8 + 4];
            *(float4*)&bf[0] = *(const float4*)&Bs[kk][tn * 4];
            #pragma unroll
            for (int i = 0; i < 8; i++)
                #pragma unroll
                for (int j = 0; j < 4; j++)
                    acc[i][j] = fmaf(af[i], bf[j], acc[i][j]);
        }
    }

    float bias[4];
    #pragma unroll
    for (int j = 0; j < 4; j++) bias[j] = __ldg(&b[tn * 4 + j]);

    #pragma unroll
    for (int i = 0; i < 8; i++) {
        int m = m0 + tm * 8 + i;
        float4 o;
        float v;
        v = __fadd_rn(__fadd_rn(accp[i][0], acc[i][0]), bias[0]); o.x = xla_gelu(v);
        v = __fadd_rn(__fadd_rn(accp[i][1], acc[i][1]), bias[1]); o.y = xla_gelu(v);
        v = __fadd_rn(__fadd_rn(accp[i][2], acc[i][2]), bias[2]); o.z = xla_gelu(v);
        v = __fadd_rn(__fadd_rn(accp[i][3], acc[i][3]), bias[3]); o.w = xla_gelu(v);
        *(float4*)&g_h[(size_t)m * CL + tn * 4] = o;
    }
}

// ---------------------------------------------------------------------------
// Kernel 2: epilogue with in-block centroid norm + smem-staged h tile.
//   - 128 tokens / block, 128 threads
//   - coalesced float4 loads of the h tile into pad-65 smem rows
//   - float4 LDS in the dot loop (chain order unchanged)
// All arithmetic chains identical to R13 (bit-exact).
// ---------------------------------------------------------------------------
#define EPB 128
// dynamic smem (floats): h_s [128][65] = 8320 | cn_s [64][64] = 4096 | cc_s 64
#define EPI_SMEM_FLOATS (8320 + 4096 + 64)

__global__ __launch_bounds__(EPB)
void router_epilogue_kernel(const float* __restrict__ centroids,
                            float* __restrict__ out) {
    extern __shared__ float sm[];
    float* h_s  = sm;            // [128][65]
    float* cn_s = sm + 8320;     // [64][64]
    float* cc_s = sm + 12416;    // [64]

    const int tid = threadIdx.x;
    const int t0  = blockIdx.x * EPB;

    // coalesced stage of the 128x64 h tile into pad-65 rows
    {
        const float4* src = (const float4*)&g_h[(size_t)t0 * CL];
        for (int idx = tid; idx < EPB * CL / 4; idx += EPB) {
            float4 v = src[idx];
            int flat = idx * 4;
            int row  = flat >> 6;
            int col  = flat & 63;
            float* dst = &h_s[row * 65 + col];
            dst[0] = v.x; dst[1] = v.y; dst[2] = v.z; dst[3] = v.w;
        }
    }

    // in-block centroid normalization (identical ops; L2-hot across blocks)
    if (tid < EXPERTS) {
        int e = tid;
        float c[CL];
        for (int j = 0; j < CL; j++) c[j] = centroids[e * CL + j];
        float ss = vsum_sq64(c);
        float nrm = fmaxf(__fsqrt_rn(ss), 1e-8f);
        float cn[CL];
        for (int j = 0; j < CL; j++) {
            cn[j] = __fdiv_rn(c[j], nrm);
            cn_s[e * CL + j] = cn[j];
        }
        cc_s[e] = vsum_sq64(cn);
    }

    __syncthreads();

    const int t = t0 + tid;

    float d[CL];
    #pragma unroll
    for (int j = 0; j < CL; j++) d[j] = h_s[tid * 65 + j];

    float ss  = vsum_sq64(d);
    float nrm = fmaxf(__fsqrt_rn(ss), 1e-8f);
    #pragma unroll
    for (int j = 0; j < CL; j++) d[j] = __fdiv_rn(d[j], nrm);
    float dd = vsum_sq64(d);

    // pass 1: -dist per expert (fused ascending dot, float4 smem reads)
    float nd[EXPERTS];
    float ndmax = -INFINITY;
    for (int e = 0; e < EXPERTS; e++) {
        const float4* ce4 = (const float4*)&cn_s[e * CL];
        float dot = 0.f;
        #pragma unroll
        for (int jj = 0; jj < CL / 4; jj++) {
            float4 c4 = ce4[jj];
            dot = fmaf(d[jj * 4 + 0], c4.x, dot);
            dot = fmaf(d[jj * 4 + 1], c4.y, dot);
            dot = fmaf(d[jj * 4 + 2], c4.z, dot);
            dot = fmaf(d[jj * 4 + 3], c4.w, dot);
        }
        float sq   = __fsub_rn(__fadd_rn(dd, cc_s[e]), __fmul_rn(2.0f, dot));
        float dist = __fsqrt_rn(fmaxf(sq, 0.0f));
        float v = -dist;
        nd[e] = v;
        ndmax = fmaxf(ndmax, v);
    }

    // pass 2: w = exp(x - xmax)
    #pragma unroll
    for (int e = 0; e < EXPERTS; e++)
        nd[e] = xla_exp(__fsub_rn(nd[e], ndmax));
    float sum = vsum64(nd);

    // pass 3: p = w / sum, stable top-2 (ties -> lower index)
    float p1 = -1.f, p2 = -1.f;
    int   i1 = 0,    i2 = 0;
    for (int e = 0; e < EXPERTS; e++) {
        float p = __fdiv_rn(nd[e], sum);
        if (p > p1)      { p2 = p1; i2 = i1; p1 = p; i1 = e; }
        else if (p > p2) { p2 = p; i2 = e; }
    }

    out[(size_t)t * 2 + 0] = p1;
    out[(size_t)t * 2 + 1] = p2;
    float* oi = out + (size_t)N_TOKENS * 2;
    oi[(size_t)t * 2 + 0] = (float)i1;
    oi[(size_t)t * 2 + 1] = (float)i2;
}

// ---------------------------------------------------------------------------
extern "C" void kernel_launch(void* const* d_in, const int* in_sizes, int n_in,
                              void* d_out, int out_size) {
    const float* x         = (const float*)d_in[0];
    const float* W         = (const float*)d_in[1];
    const float* b         = (const float*)d_in[2];
    const float* centroids = (const float*)d_in[3];
    float* out = (float*)d_out;

    gemm_gelu_kernel<<<N_TOKENS / BM, 256>>>(x, W, b);

    cudaFuncSetAttribute(router_epilogue_kernel,
                         cudaFuncAttributeMaxDynamicSharedMemorySize,
                         EPI_SMEM_FLOATS * (int)sizeof(float));
    router_epilogue_kernel<<<N_TOKENS / EPB, EPB,
                             EPI_SMEM_FLOATS * sizeof(float)>>>(centroids, out);
}